// round 2
// baseline (speedup 1.0000x reference)
#include <cuda_runtime.h>
#include <cstddef>

// Problem constants (fixed by the dataset)
#define TBL 32   // T
#define DIM 64   // D

// One warp per bag. Lane l accumulates output elements [2l, 2l+1] (float2).
// Row of the table is 64 floats = 256 B, exactly one warp-wide float2 read.
__global__ void __launch_bounds__(256, 8)
embbag_kernel(const float* __restrict__ W,
              const int*   __restrict__ feat,
              const int*   __restrict__ off,
              float*       __restrict__ out,
              int num_bags)
{
    int gwarp = (blockIdx.x * blockDim.x + threadIdx.x) >> 5;
    int lane  = threadIdx.x & 31;
    if (gwarp >= num_bags) return;

    const int table = gwarp & (TBL - 1);     // bag % T, T = 32
    const int start = off[gwarp];
    const int end   = off[gwarp + 1];

    float ax = 0.f, ay = 0.f;

    int j = start;
    // Unroll x4: four independent gathers in flight per lane.
    for (; j + 4 <= end; j += 4) {
        int e0 = __ldg(feat + j + 0);
        int e1 = __ldg(feat + j + 1);
        int e2 = __ldg(feat + j + 2);
        int e3 = __ldg(feat + j + 3);
        const float2* r0 = (const float2*)(W + ((size_t)e0 * TBL + table) * DIM);
        const float2* r1 = (const float2*)(W + ((size_t)e1 * TBL + table) * DIM);
        const float2* r2 = (const float2*)(W + ((size_t)e2 * TBL + table) * DIM);
        const float2* r3 = (const float2*)(W + ((size_t)e3 * TBL + table) * DIM);
        float2 v0 = __ldg(r0 + lane);
        float2 v1 = __ldg(r1 + lane);
        float2 v2 = __ldg(r2 + lane);
        float2 v3 = __ldg(r3 + lane);
        ax += v0.x + v1.x + v2.x + v3.x;
        ay += v0.y + v1.y + v2.y + v3.y;
    }
    for (; j < end; ++j) {
        int e = __ldg(feat + j);
        const float2* r = (const float2*)(W + ((size_t)e * TBL + table) * DIM);
        float2 v = __ldg(r + lane);
        ax += v.x;
        ay += v.y;
    }

    float2* o = (float2*)(out + (size_t)gwarp * DIM);
    o[lane] = make_float2(ax, ay);
}

extern "C" void kernel_launch(void* const* d_in, const int* in_sizes, int n_in,
                              void* d_out, int out_size)
{
    const float* W    = (const float*)d_in[0];   // (E, T, D) fp32
    const int*   feat = (const int*)d_in[1];     // (B*T*L,) int32
    const int*   off  = (const int*)d_in[2];     // (B*T+1,) int32

    int num_bags = in_sizes[2] - 1;              // B*T = 32768
    float* out = (float*)d_out;                  // (B, T, D) fp32

    int threads = 256;                           // 8 warps = 8 bags per block
    int total_threads = num_bags * 32;
    int blocks = (total_threads + threads - 1) / threads;

    embbag_kernel<<<blocks, threads>>>(W, feat, off, out, num_bags);
}

// round 4
// speedup vs baseline: 1.0625x; 1.0625x over previous
#include <cuda_runtime.h>
#include <cstddef>

// Problem constants (fixed by the dataset)
#define TBL 32      // T
#define DIM 64      // D
#define GRP 1024    // bags per table value = num_bags / TBL

// One warp per bag. Lane l accumulates output elements [2l, 2l+1] (float2).
// Warps are remapped so that bags sharing the same table slice W[:, t, :]
// run temporally adjacent -> their 25.6MB slice (~10MB touched) stays in L2
// and repeated indices become L2 hits instead of DRAM fetches.
__global__ void __launch_bounds__(256, 8)
embbag_kernel(const float* __restrict__ W,
              const int*   __restrict__ feat,
              const int*   __restrict__ off,
              float*       __restrict__ out,
              int num_bags)
{
    int gwarp = (blockIdx.x * blockDim.x + threadIdx.x) >> 5;
    int lane  = threadIdx.x & 31;
    if (gwarp >= num_bags) return;

    // Table-grouped schedule: warps [t*GRP, (t+1)*GRP) handle table t.
    const int table = gwarp >> 10;           // g / 1024
    const int group = gwarp & (GRP - 1);     // g % 1024
    const int bag   = (group << 5) + table;  // original bag id; bag % 32 == table

    const int start = off[bag];
    const int end   = off[bag + 1];

    float ax = 0.f, ay = 0.f;

    int j = start;
    // Unroll x4: four independent gathers in flight per lane.
    for (; j + 4 <= end; j += 4) {
        int e0 = __ldg(feat + j + 0);
        int e1 = __ldg(feat + j + 1);
        int e2 = __ldg(feat + j + 2);
        int e3 = __ldg(feat + j + 3);
        const float2* r0 = (const float2*)(W + ((size_t)e0 * TBL + table) * DIM);
        const float2* r1 = (const float2*)(W + ((size_t)e1 * TBL + table) * DIM);
        const float2* r2 = (const float2*)(W + ((size_t)e2 * TBL + table) * DIM);
        const float2* r3 = (const float2*)(W + ((size_t)e3 * TBL + table) * DIM);
        float2 v0 = __ldg(r0 + lane);
        float2 v1 = __ldg(r1 + lane);
        float2 v2 = __ldg(r2 + lane);
        float2 v3 = __ldg(r3 + lane);
        ax += v0.x + v1.x + v2.x + v3.x;
        ay += v0.y + v1.y + v2.y + v3.y;
    }
    for (; j < end; ++j) {
        int e = __ldg(feat + j);
        const float2* r = (const float2*)(W + ((size_t)e * TBL + table) * DIM);
        float2 v = __ldg(r + lane);
        ax += v.x;
        ay += v.y;
    }

    // Streaming store: don't let the 8MB output evict hot table rows in L2.
    float2* o = (float2*)(out + (size_t)bag * DIM);
    __stcs(o + lane, make_float2(ax, ay));
}

extern "C" void kernel_launch(void* const* d_in, const int* in_sizes, int n_in,
                              void* d_out, int out_size)
{
    const float* W    = (const float*)d_in[0];   // (E, T, D) fp32
    const int*   feat = (const int*)d_in[1];     // (B*T*L,) int32
    const int*   off  = (const int*)d_in[2];     // (B*T+1,) int32

    int num_bags = in_sizes[2] - 1;              // B*T = 32768
    float* out = (float*)d_out;                  // (B, T, D) fp32

    int threads = 256;                           // 8 warps = 8 bags per block
    int total_threads = num_bags * 32;
    int blocks = (total_threads + threads - 1) / threads;

    embbag_kernel<<<blocks, threads>>>(W, feat, off, out, num_bags);
}